// round 9
// baseline (speedup 1.0000x reference)
#include <cuda_runtime.h>
#include <cuda_bf16.h>
#include <cstdint>

// Problem constants
#define T_DIM 512
#define B_DIM 128
#define I_DIM 512
#define H_DIM 1024
#define BH (B_DIM * H_DIM)

// ---------------- scratch (static device globals: allocation-free) ----------
__device__ float g_pre[T_DIM * B_DIM * H_DIM];            // 268 MB, reused
__device__ float g_sx1[(T_DIM - 1) * B_DIM * I_DIM];      // layer-1 scaled input
__device__ unsigned g_bar4[4 * 64];                       // per-rowgroup barrier counters
// h state as pre-split bf16, double-buffered across steps
__device__ __nv_bfloat16 g_hhi[2 * BH], g_hlo[2 * BH];
// transposed + bf16-split weights: [N][K] row-major, K contiguous
__device__ __nv_bfloat16 g_w0t_hi[H_DIM * I_DIM], g_w0t_lo[H_DIM * I_DIM];
__device__ __nv_bfloat16 g_wi1t_hi[H_DIM * H_DIM], g_wi1t_lo[H_DIM * H_DIM];
__device__ __nv_bfloat16 g_ws1t_hi[H_DIM * I_DIM], g_ws1t_lo[H_DIM * I_DIM];

// ---------------- cp.async helpers -----------------------------------------
__device__ __forceinline__ void cp_async16(void* sdst, const void* gsrc) {
    unsigned s = (unsigned)__cvta_generic_to_shared(sdst);
    asm volatile("cp.async.cg.shared.global [%0], [%1], 16;" :: "r"(s), "l"(gsrc));
}
__device__ __forceinline__ void cp_commit() {
    asm volatile("cp.async.commit_group;" ::: "memory");
}
template <int N>
__device__ __forceinline__ void cp_wait() {
    asm volatile("cp.async.wait_group %0;" :: "n"(N) : "memory");
}

__device__ __forceinline__ void mma_bf16(float* c, const uint32_t* a, const uint32_t* b) {
    asm volatile(
        "mma.sync.aligned.m16n8k16.row.col.f32.bf16.bf16.f32 "
        "{%0,%1,%2,%3}, {%4,%5,%6,%7}, {%8,%9}, {%0,%1,%2,%3};"
        : "+f"(c[0]), "+f"(c[1]), "+f"(c[2]), "+f"(c[3])
        : "r"(a[0]), "r"(a[1]), "r"(a[2]), "r"(a[3]), "r"(b[0]), "r"(b[1]));
}

// ---------------- small elementwise kernels --------------------------------
__global__ void k_sx1(const float* __restrict__ x, float* __restrict__ o,
                      int n, int off) {
    int i = blockIdx.x * 256 + threadIdx.x;
    if (i < n) o[i] = 0.5f * (x[i] + x[i + off]);
}
__global__ void k_reset_bar() {
    if (threadIdx.x < 4 * 64) g_bar4[threadIdx.x] = 0u;
}

// transpose + bf16 hi/lo split: W[K,N] (+optional W2) -> Thi/Tlo [N,K]
__global__ void k_tsplit(const float* __restrict__ W, const float* __restrict__ W2,
                         __nv_bfloat16* __restrict__ Thi, __nv_bfloat16* __restrict__ Tlo,
                         int K, int N) {
    __shared__ float s[32][33];
    int k0 = blockIdx.x * 32, n0 = blockIdx.y * 32;
    int tx = threadIdx.x, ty = threadIdx.y;   // 32 x 8
#pragma unroll
    for (int i = 0; i < 4; i++) {
        int k = k0 + ty + i * 8;
        float v = W[(size_t)k * N + n0 + tx];
        if (W2) v += W2[(size_t)k * N + n0 + tx];
        s[ty + i * 8][tx] = v;
    }
    __syncthreads();
#pragma unroll
    for (int i = 0; i < 4; i++) {
        int n = n0 + ty + i * 8;
        float v = s[tx][ty + i * 8];
        __nv_bfloat16 h = __float2bfloat16(v);
        Thi[(size_t)n * K + k0 + tx] = h;
        Tlo[(size_t)n * K + k0 + tx] = __float2bfloat16(v - __bfloat162float(h));
    }
}

// ---------------- HMMA split-bf16 GEMM (unchanged, proven R4) ---------------
#define PITCH 40
#define TILE_HL (128 * PITCH)
#define SM_A 0
#define SM_B (4 * TILE_HL)
#define SM_TOTAL_BF16 (8 * TILE_HL)

__global__ __launch_bounds__(256) void tc_gemm(
    float* __restrict__ C,
    const float* __restrict__ A0, int K0,
    const __nv_bfloat16* __restrict__ B0hi, const __nv_bfloat16* __restrict__ B0lo,
    const float* __restrict__ A1, int K1,
    const __nv_bfloat16* __restrict__ B1hi, const __nv_bfloat16* __restrict__ B1lo)
{
    extern __shared__ __align__(16) __nv_bfloat16 sm[];
    const int tid = threadIdx.x;
    const int wid = tid >> 5, lane = tid & 31;
    const int g = lane >> 2, tg = lane & 3;
    const int wm = (wid >> 2) * 64, wn = (wid & 3) * 32;
    const int mrow0 = blockIdx.y * 128;
    const int ncol0 = blockIdx.x * 128;

    const int NI0 = K0 / 32;
    const int NI = NI0 + K1 / 32;

    float acc[4][4][4];
#pragma unroll
    for (int i = 0; i < 4; i++)
#pragma unroll
        for (int j = 0; j < 4; j++)
#pragma unroll
            for (int q = 0; q < 4; q++) acc[i][j][q] = 0.f;

    const int ar = tid >> 1, ah = (tid & 1) * 16;
    const int bhl = tid >> 7, br = tid & 127;

#define A_SRC(A, K, koff) ((const float4*)((A) + (size_t)(mrow0 + ar) * (K) + (koff) + ah))
#define STS_A(buf, st)                                                                 \
    {                                                                                  \
        __nv_bfloat16* dh = sm + SM_A + ((buf) * 2 + 0) * TILE_HL + ar * PITCH + ah;   \
        __nv_bfloat16* dl = sm + SM_A + ((buf) * 2 + 1) * TILE_HL + ar * PITCH + ah;   \
        _Pragma("unroll")                                                              \
        for (int q = 0; q < 4; q++) {                                                  \
            float f[4] = {st[q].x, st[q].y, st[q].z, st[q].w};                         \
            uint32_t hi2[2], lo2[2];                                                   \
            _Pragma("unroll")                                                          \
            for (int j = 0; j < 2; j++) {                                              \
                __nv_bfloat16 h0 = __float2bfloat16(f[2 * j]);                         \
                __nv_bfloat16 h1 = __float2bfloat16(f[2 * j + 1]);                     \
                __nv_bfloat16 l0 = __float2bfloat16(f[2 * j] - __bfloat162float(h0));  \
                __nv_bfloat16 l1 = __float2bfloat16(f[2 * j + 1] - __bfloat162float(h1)); \
                hi2[j] = (uint32_t)__bfloat16_as_ushort(h0) |                          \
                         ((uint32_t)__bfloat16_as_ushort(h1) << 16);                   \
                lo2[j] = (uint32_t)__bfloat16_as_ushort(l0) |                          \
                         ((uint32_t)__bfloat16_as_ushort(l1) << 16);                   \
            }                                                                          \
            *(uint2*)(dh + q * 4) = make_uint2(hi2[0], hi2[1]);                        \
            *(uint2*)(dl + q * 4) = make_uint2(lo2[0], lo2[1]);                        \
        }                                                                              \
    }
#define LOAD_B(buf, Bhi, Blo, K, koff)                                                 \
    {                                                                                  \
        const __nv_bfloat16* src = ((bhl) ? (Blo) : (Bhi)) +                           \
                                   (size_t)(ncol0 + br) * (K) + (koff);                \
        __nv_bfloat16* dst = sm + SM_B + ((buf) * 2 + bhl) * TILE_HL + br * PITCH;     \
        _Pragma("unroll")                                                              \
        for (int q = 0; q < 4; q++) cp_async16(dst + q * 8, src + q * 8);              \
    }

    {
        float4 st[4];
        const float4* s4 = A_SRC(A0, K0, 0);
#pragma unroll
        for (int q = 0; q < 4; q++) st[q] = s4[q];
        STS_A(0, st);
        LOAD_B(0, B0hi, B0lo, K0, 0);
        cp_commit();
    }

    for (int i = 0; i < NI; i++) {
        cp_wait<0>();
        __syncthreads();

        const int buf = i & 1;
        float4 st[4];
        bool have_next = (i + 1 < NI);
        if (have_next) {
            int ni = i + 1;
            if (ni < NI0) {
                const float4* s4 = A_SRC(A0, K0, ni * 32);
#pragma unroll
                for (int q = 0; q < 4; q++) st[q] = s4[q];
                LOAD_B(buf ^ 1, B0hi, B0lo, K0, ni * 32);
            } else {
                int koff = (ni - NI0) * 32;
                const float4* s4 = A_SRC(A1, K1, koff);
#pragma unroll
                for (int q = 0; q < 4; q++) st[q] = s4[q];
                LOAD_B(buf ^ 1, B1hi, B1lo, K1, koff);
            }
            cp_commit();
        }

        const __nv_bfloat16* sAh = sm + SM_A + (buf * 2 + 0) * TILE_HL;
        const __nv_bfloat16* sAl = sm + SM_A + (buf * 2 + 1) * TILE_HL;
        const __nv_bfloat16* sBh = sm + SM_B + (buf * 2 + 0) * TILE_HL;
        const __nv_bfloat16* sBl = sm + SM_B + (buf * 2 + 1) * TILE_HL;
#pragma unroll
        for (int kk = 0; kk < 32; kk += 16) {
            uint32_t bh[4][2], bl[4][2];
#pragma unroll
            for (int nt = 0; nt < 4; nt++) {
                int n = wn + nt * 8 + g;
                bh[nt][0] = *(const uint32_t*)(sBh + n * PITCH + kk + tg * 2);
                bh[nt][1] = *(const uint32_t*)(sBh + n * PITCH + kk + tg * 2 + 8);
                bl[nt][0] = *(const uint32_t*)(sBl + n * PITCH + kk + tg * 2);
                bl[nt][1] = *(const uint32_t*)(sBl + n * PITCH + kk + tg * 2 + 8);
            }
#pragma unroll
            for (int mt = 0; mt < 4; mt++) {
                int r = wm + mt * 16 + g;
                uint32_t a_hi[4], a_lo[4];
                a_hi[0] = *(const uint32_t*)(sAh + r * PITCH + kk + tg * 2);
                a_hi[1] = *(const uint32_t*)(sAh + (r + 8) * PITCH + kk + tg * 2);
                a_hi[2] = *(const uint32_t*)(sAh + r * PITCH + kk + tg * 2 + 8);
                a_hi[3] = *(const uint32_t*)(sAh + (r + 8) * PITCH + kk + tg * 2 + 8);
                a_lo[0] = *(const uint32_t*)(sAl + r * PITCH + kk + tg * 2);
                a_lo[1] = *(const uint32_t*)(sAl + (r + 8) * PITCH + kk + tg * 2);
                a_lo[2] = *(const uint32_t*)(sAl + r * PITCH + kk + tg * 2 + 8);
                a_lo[3] = *(const uint32_t*)(sAl + (r + 8) * PITCH + kk + tg * 2 + 8);
#pragma unroll
                for (int nt = 0; nt < 4; nt++) {
                    mma_bf16(acc[mt][nt], a_hi, bh[nt]);
                    mma_bf16(acc[mt][nt], a_lo, bh[nt]);
                    mma_bf16(acc[mt][nt], a_hi, bl[nt]);
                }
            }
        }

        if (have_next) STS_A(buf ^ 1, st);
    }

#pragma unroll
    for (int mt = 0; mt < 4; mt++) {
#pragma unroll
        for (int nt = 0; nt < 4; nt++) {
            int r0 = mrow0 + wm + mt * 16 + g;
            int c0 = ncol0 + wn + nt * 8 + tg * 2;
            *(float2*)(C + (size_t)r0 * 1024 + c0) =
                make_float2(acc[mt][nt][0], acc[mt][nt][1]);
            *(float2*)(C + (size_t)(r0 + 8) * 1024 + c0) =
                make_float2(acc[mt][nt][2], acc[mt][nt][3]);
        }
    }
#undef A_SRC
#undef STS_A
#undef LOAD_B
}

// ---------------- HMMA persistent recurrence v4 (warp-local pipeline) --------
// 128 blocks, 32x32 tile (rg = bid>>5 batch rows, cg = bid&31 H cols). 8 warps,
// each a full 32x32 warp tile over its K=128 slice. h chunks are WARP-LOCAL:
// warp w streams only its 32x32 K-slice of each K=256 chunk into a private
// double-buffered SMEM ring via its own cp.async groups -> zero block syncs in
// the chunk loop. Cross-warp K-reduce via SMEM (3 block syncs per step total).
#define R4_WP 1032
#define R4_SW (32 * R4_WP)              // weight strip elems (one of hi/lo)
#define R4_HP 40                        // warp h-slice row pitch (80B, 16B-aligned)
#define R4_SLICE (32 * R4_HP)           // 1280 elems: one 32x32 hl slice
#define R4_WARPBUF (4 * R4_SLICE)       // 2 ring slots x (hi+lo) = 5120 elems
#define R4_RING_OFF (2 * R4_SW)         // elems; ring base
#define R4_RED_BYTE (R4_RING_OFF * 2)   // red aliases ring (sync-guarded)
#define R4_RPITCH 34
#define R4_RW (32 * R4_RPITCH)
#define R4_PRE_BYTE ((R4_RING_OFF + 8 * R4_WARPBUF) * 2)   // 213 KB
#define R4_BYTES (R4_PRE_BYTE + 4096 + 128)

__global__ __launch_bounds__(256, 1) void recur4(
    const float* __restrict__ pre, float* __restrict__ out,
    const float* __restrict__ Wh,
    __nv_bfloat16* __restrict__ hhi, __nv_bfloat16* __restrict__ hlo,
    int steps)
{
    extern __shared__ __align__(16) __nv_bfloat16 sm2[];
    float* red  = (float*)((char*)sm2 + R4_RED_BYTE);
    float* preS = (float*)((char*)sm2 + R4_PRE_BYTE);
    const int tid = threadIdx.x, wid = tid >> 5, lane = tid & 31;
    const int g = lane >> 2, tg = lane & 3;
    const int rg = blockIdx.x >> 5;
    const int r0 = rg * 32;
    const int c0 = (blockIdx.x & 31) * 32;
    __nv_bfloat16* wbuf = sm2 + R4_RING_OFF + wid * R4_WARPBUF;

    // ---- load + split Wh strip into SMEM once ----
    for (int k = wid; k < H_DIM; k += 8) {
        float w = Wh[(size_t)k * H_DIM + c0 + lane];
        __nv_bfloat16 h = __float2bfloat16(w);
        sm2[lane * R4_WP + k] = h;
        sm2[R4_SW + lane * R4_WP + k] = __float2bfloat16(w - __bfloat162float(h));
    }
    __syncthreads();

    unsigned target = 0;
    volatile unsigned* vb = &g_bar4[rg * 64];

    // warp-local h slice load: chunk c -> ring slot (c&1). 8 cp.async/thread.
#define ISSUE_W(c, hp)                                                                   \
    {                                                                                    \
        __nv_bfloat16* dst = wbuf + ((c) & 1) * (2 * R4_SLICE);                          \
        const size_t gb = (size_t)(hp)*BH + (size_t)(r0 + lane) * H_DIM +                \
                          (c)*256 + wid * 32;                                            \
        _Pragma("unroll")                                                                \
        for (int i = 0; i < 4; i++) {                                                    \
            cp_async16(dst + lane * R4_HP + i * 8, hhi + gb + i * 8);                    \
            cp_async16(dst + R4_SLICE + lane * R4_HP + i * 8, hlo + gb + i * 8);         \
        }                                                                                \
        cp_commit();                                                                     \
    }
#define ISSUE_PRE(tt)                                                                    \
    {                                                                                    \
        int row = tid >> 3, seg = tid & 7;                                               \
        cp_async16(preS + row * 32 + seg * 4,                                            \
                   pre + (size_t)(tt)*BH + (size_t)(r0 + row) * H_DIM + c0 + seg * 4);   \
        cp_commit();                                                                     \
    }

    for (int t = 0; t < steps; t++) {
        float acc[2][4][4];
#pragma unroll
        for (int mt = 0; mt < 2; mt++)
#pragma unroll
            for (int nt = 0; nt < 4; nt++)
#pragma unroll
                for (int q = 0; q < 4; q++) acc[mt][nt][q] = 0.f;

        if (t > 0) {
            const int hp = (t - 1) & 1;
            ISSUE_W(0, hp);
            ISSUE_W(1, hp);
            ISSUE_PRE(t);
#pragma unroll 1
            for (int c = 0; c < 4; c++) {
                // per-warp wait: groups complete in order; pre group rides along
                if (c == 0) cp_wait<2>();
                else if (c == 1) cp_wait<2>();
                else if (c == 2) cp_wait<1>();
                else cp_wait<0>();

                const __nv_bfloat16* sAh = wbuf + (c & 1) * (2 * R4_SLICE);
                const __nv_bfloat16* sAl = sAh + R4_SLICE;
#pragma unroll
                for (int kt = 0; kt < 2; kt++) {
                    const int kk = kt * 16;
                    const int kgl = c * 256 + wid * 32 + kk;
                    uint32_t ah[2][4], al[2][4];
#pragma unroll
                    for (int mt = 0; mt < 2; mt++) {
                        const int ra = (mt * 16 + g) * R4_HP + kk + tg * 2;
                        const int rb = (mt * 16 + g + 8) * R4_HP + kk + tg * 2;
                        ah[mt][0] = *(const uint32_t*)(sAh + ra);
                        ah[mt][1] = *(const uint32_t*)(sAh + rb);
                        ah[mt][2] = *(const uint32_t*)(sAh + ra + 8);
                        ah[mt][3] = *(const uint32_t*)(sAh + rb + 8);
                        al[mt][0] = *(const uint32_t*)(sAl + ra);
                        al[mt][1] = *(const uint32_t*)(sAl + rb);
                        al[mt][2] = *(const uint32_t*)(sAl + ra + 8);
                        al[mt][3] = *(const uint32_t*)(sAl + rb + 8);
                    }
#pragma unroll
                    for (int nt = 0; nt < 4; nt++) {
                        const int nb = (nt * 8 + g) * R4_WP + kgl + tg * 2;
                        uint32_t bh[2], bl[2];
                        bh[0] = *(const uint32_t*)(sm2 + nb);
                        bh[1] = *(const uint32_t*)(sm2 + nb + 8);
                        bl[0] = *(const uint32_t*)(sm2 + R4_SW + nb);
                        bl[1] = *(const uint32_t*)(sm2 + R4_SW + nb + 8);
#pragma unroll
                        for (int mt = 0; mt < 2; mt++) {
                            mma_bf16(acc[mt][nt], ah[mt], bh);
                            mma_bf16(acc[mt][nt], al[mt], bh);
                            mma_bf16(acc[mt][nt], ah[mt], bl);
                        }
                    }
                }
                if (c < 2) ISSUE_W(c + 2, hp);
            }
            // all warps done with ring before red (aliases ring)
            __syncthreads();
            float* rw = red + wid * R4_RW;
#pragma unroll
            for (int mt = 0; mt < 2; mt++)
#pragma unroll
                for (int nt = 0; nt < 4; nt++) {
                    int row = mt * 16 + g, col = nt * 8 + tg * 2;
                    *(float2*)(rw + row * R4_RPITCH + col) =
                        make_float2(acc[mt][nt][0], acc[mt][nt][1]);
                    *(float2*)(rw + (row + 8) * R4_RPITCH + col) =
                        make_float2(acc[mt][nt][2], acc[mt][nt][3]);
                }
            __syncthreads();
        } else {
            ISSUE_PRE(0);
            cp_wait<0>();
        }

        // ---- reduce + epilogue: 4 outputs per thread (thread-private pre) ----
        {
            const int row = tid >> 3, cseg = (tid & 7) * 4;
            float4 s = make_float4(0.f, 0.f, 0.f, 0.f);
            if (t > 0) {
#pragma unroll
                for (int w = 0; w < 8; w++) {
                    const float* rp = red + w * R4_RW + row * R4_RPITCH + cseg;
                    s.x += rp[0]; s.y += rp[1]; s.z += rp[2]; s.w += rp[3];
                }
            }
            const float4 p = *(const float4*)(preS + row * 32 + cseg);
            float v0 = tanhf(p.x + s.x), v1 = tanhf(p.y + s.y);
            float v2 = tanhf(p.z + s.z), v3 = tanhf(p.w + s.w);
            const size_t gidx = (size_t)(r0 + row) * H_DIM + c0 + cseg;
            *(float4*)(out + (size_t)t * BH + gidx) = make_float4(v0, v1, v2, v3);

            __nv_bfloat16 h0 = __float2bfloat16(v0), h1 = __float2bfloat16(v1);
            __nv_bfloat16 h2 = __float2bfloat16(v2), h3 = __float2bfloat16(v3);
            __nv_bfloat16 l0 = __float2bfloat16(v0 - __bfloat162float(h0));
            __nv_bfloat16 l1 = __float2bfloat16(v1 - __bfloat162float(h1));
            __nv_bfloat16 l2 = __float2bfloat16(v2 - __bfloat162float(h2));
            __nv_bfloat16 l3 = __float2bfloat16(v3 - __bfloat162float(h3));
            const size_t hidx = (size_t)(t & 1) * BH + gidx;
            *(uint2*)(hhi + hidx) = make_uint2(
                (uint32_t)__bfloat16_as_ushort(h0) | ((uint32_t)__bfloat16_as_ushort(h1) << 16),
                (uint32_t)__bfloat16_as_ushort(h2) | ((uint32_t)__bfloat16_as_ushort(h3) << 16));
            *(uint2*)(hlo + hidx) = make_uint2(
                (uint32_t)__bfloat16_as_ushort(l0) | ((uint32_t)__bfloat16_as_ushort(l1) << 16),
                (uint32_t)__bfloat16_as_ushort(l2) | ((uint32_t)__bfloat16_as_ushort(l3) << 16));
        }

        if (t + 1 < steps) {
            __threadfence();
            target += 32;
            if (tid == 0) {
                atomicAdd((unsigned*)vb, 1u);
                while (*vb < target) __nanosleep(32);
            }
            __syncthreads();
        }
    }
#undef ISSUE_W
#undef ISSUE_PRE
}

// ---------------- launch ----------------------------------------------------
extern "C" void kernel_launch(void* const* d_in, const int* in_sizes, int n_in,
                              void* d_out, int out_size)
{
    (void)in_sizes; (void)n_in; (void)out_size;
    const float* x   = (const float*)d_in[0];
    const float* Wi0 = (const float*)d_in[1];
    const float* Wh0 = (const float*)d_in[2];
    const float* Ws0 = (const float*)d_in[3];
    const float* Wi1 = (const float*)d_in[4];
    const float* Wh1 = (const float*)d_in[5];
    const float* Ws1 = (const float*)d_in[6];
    float* out = (float*)d_out;

    void* p;
    cudaGetSymbolAddress(&p, g_pre);     float* pre = (float*)p;
    cudaGetSymbolAddress(&p, g_sx1);     float* sx1 = (float*)p;
    cudaGetSymbolAddress(&p, g_hhi);     __nv_bfloat16* hhi = (__nv_bfloat16*)p;
    cudaGetSymbolAddress(&p, g_hlo);     __nv_bfloat16* hlo = (__nv_bfloat16*)p;
    cudaGetSymbolAddress(&p, g_w0t_hi);  __nv_bfloat16* w0hi = (__nv_bfloat16*)p;
    cudaGetSymbolAddress(&p, g_w0t_lo);  __nv_bfloat16* w0lo = (__nv_bfloat16*)p;
    cudaGetSymbolAddress(&p, g_wi1t_hi); __nv_bfloat16* wi1hi = (__nv_bfloat16*)p;
    cudaGetSymbolAddress(&p, g_wi1t_lo); __nv_bfloat16* wi1lo = (__nv_bfloat16*)p;
    cudaGetSymbolAddress(&p, g_ws1t_hi); __nv_bfloat16* ws1hi = (__nv_bfloat16*)p;
    cudaGetSymbolAddress(&p, g_ws1t_lo); __nv_bfloat16* ws1lo = (__nv_bfloat16*)p;

    cudaFuncSetAttribute(recur4,
                         cudaFuncAttributeMaxDynamicSharedMemorySize, R4_BYTES);
    cudaFuncSetAttribute(tc_gemm,
                         cudaFuncAttributeMaxDynamicSharedMemorySize,
                         SM_TOTAL_BF16 * 2);

    // weight prep: transpose + bf16 hi/lo split
    dim3 tb(32, 8);
    k_tsplit<<<dim3(I_DIM / 32, H_DIM / 32), tb>>>(Wi0, Ws0, w0hi, w0lo, I_DIM, H_DIM);
    k_tsplit<<<dim3(H_DIM / 32, H_DIM / 32), tb>>>(Wi1, nullptr, wi1hi, wi1lo, H_DIM, H_DIM);
    k_tsplit<<<dim3(I_DIM / 32, H_DIM / 32), tb>>>(Ws1, nullptr, ws1hi, ws1lo, I_DIM, H_DIM);

    // layer 0: pre0 = x @ (Wi0+Ws0)
    tc_gemm<<<dim3(H_DIM / 128, (T_DIM * B_DIM) / 128), 256, SM_TOTAL_BF16 * 2>>>(
        pre, x, I_DIM, w0hi, w0lo, nullptr, 0, nullptr, nullptr);

    k_reset_bar<<<1, 256>>>();
    recur4<<<128, 256, R4_BYTES>>>(pre, out, Wh0, hhi, hlo, T_DIM);

    // layer 1: pre1 = out0[1:] @ Wi1 + sx1 @ Ws1  (fused)
    int nsx = (T_DIM - 1) * B_DIM * I_DIM;
    k_sx1<<<(nsx + 255) / 256, 256>>>(x, sx1, nsx, B_DIM * I_DIM);
    tc_gemm<<<dim3(H_DIM / 128, ((T_DIM - 1) * B_DIM) / 128), 256, SM_TOTAL_BF16 * 2>>>(
        pre, out + BH, H_DIM, wi1hi, wi1lo, sx1, I_DIM, ws1hi, ws1lo);

    k_reset_bar<<<1, 256>>>();
    recur4<<<128, 256, R4_BYTES>>>(pre, out + (size_t)T_DIM * BH, Wh1, hhi, hlo, T_DIM - 1);
}

// round 10
// speedup vs baseline: 1.3642x; 1.3642x over previous
#include <cuda_runtime.h>
#include <cuda_bf16.h>
#include <cstdint>

// Problem constants
#define T_DIM 512
#define B_DIM 128
#define I_DIM 512
#define H_DIM 1024
#define BH (B_DIM * H_DIM)

// ---------------- scratch (static device globals: allocation-free) ----------
__device__ float g_pre[T_DIM * B_DIM * H_DIM];            // 268 MB, reused
__device__ float g_sx1[(T_DIM - 1) * B_DIM * I_DIM];      // layer-1 scaled input
__device__ unsigned g_bar4[4 * 64];                       // per-rowgroup barrier counters
// h state as pre-split bf16, double-buffered across steps
__device__ __nv_bfloat16 g_hhi[2 * BH], g_hlo[2 * BH];
// transposed + bf16-split weights: [N][K] row-major, K contiguous
__device__ __nv_bfloat16 g_w0t_hi[H_DIM * I_DIM], g_w0t_lo[H_DIM * I_DIM];
__device__ __nv_bfloat16 g_wi1t_hi[H_DIM * H_DIM], g_wi1t_lo[H_DIM * H_DIM];
__device__ __nv_bfloat16 g_ws1t_hi[H_DIM * I_DIM], g_ws1t_lo[H_DIM * I_DIM];

// ---------------- cp.async helpers -----------------------------------------
__device__ __forceinline__ void cp_async16(void* sdst, const void* gsrc) {
    unsigned s = (unsigned)__cvta_generic_to_shared(sdst);
    asm volatile("cp.async.cg.shared.global [%0], [%1], 16;" :: "r"(s), "l"(gsrc));
}
__device__ __forceinline__ void cp_commit() {
    asm volatile("cp.async.commit_group;" ::: "memory");
}
template <int N>
__device__ __forceinline__ void cp_wait() {
    asm volatile("cp.async.wait_group %0;" :: "n"(N) : "memory");
}

__device__ __forceinline__ void mma_bf16(float* c, const uint32_t* a, const uint32_t* b) {
    asm volatile(
        "mma.sync.aligned.m16n8k16.row.col.f32.bf16.bf16.f32 "
        "{%0,%1,%2,%3}, {%4,%5,%6,%7}, {%8,%9}, {%0,%1,%2,%3};"
        : "+f"(c[0]), "+f"(c[1]), "+f"(c[2]), "+f"(c[3])
        : "r"(a[0]), "r"(a[1]), "r"(a[2]), "r"(a[3]), "r"(b[0]), "r"(b[1]));
}

// ---------------- small elementwise kernels --------------------------------
__global__ void k_sx1(const float* __restrict__ x, float* __restrict__ o,
                      int n, int off) {
    int i = blockIdx.x * 256 + threadIdx.x;
    if (i < n) o[i] = 0.5f * (x[i] + x[i + off]);
}
__global__ void k_reset_bar() {
    if (threadIdx.x < 4 * 64) g_bar4[threadIdx.x] = 0u;
}

// transpose + bf16 hi/lo split: W[K,N] (+optional W2) -> Thi/Tlo [N,K]
__global__ void k_tsplit(const float* __restrict__ W, const float* __restrict__ W2,
                         __nv_bfloat16* __restrict__ Thi, __nv_bfloat16* __restrict__ Tlo,
                         int K, int N) {
    __shared__ float s[32][33];
    int k0 = blockIdx.x * 32, n0 = blockIdx.y * 32;
    int tx = threadIdx.x, ty = threadIdx.y;   // 32 x 8
#pragma unroll
    for (int i = 0; i < 4; i++) {
        int k = k0 + ty + i * 8;
        float v = W[(size_t)k * N + n0 + tx];
        if (W2) v += W2[(size_t)k * N + n0 + tx];
        s[ty + i * 8][tx] = v;
    }
    __syncthreads();
#pragma unroll
    for (int i = 0; i < 4; i++) {
        int n = n0 + ty + i * 8;
        float v = s[tx][ty + i * 8];
        __nv_bfloat16 h = __float2bfloat16(v);
        Thi[(size_t)n * K + k0 + tx] = h;
        Tlo[(size_t)n * K + k0 + tx] = __float2bfloat16(v - __bfloat162float(h));
    }
}

// ---------------- HMMA split-bf16 GEMM: 512 threads, warp tile 32x32 --------
#define PITCH 40
#define TILE_HL (128 * PITCH)
#define SM_A 0
#define SM_B (4 * TILE_HL)
#define SM_TOTAL_BF16 (8 * TILE_HL)

__global__ __launch_bounds__(512) void tc_gemm(
    float* __restrict__ C,
    const float* __restrict__ A0, int K0,
    const __nv_bfloat16* __restrict__ B0hi, const __nv_bfloat16* __restrict__ B0lo,
    const float* __restrict__ A1, int K1,
    const __nv_bfloat16* __restrict__ B1hi, const __nv_bfloat16* __restrict__ B1lo)
{
    extern __shared__ __align__(16) __nv_bfloat16 sm[];
    const int tid = threadIdx.x;
    const int wid = tid >> 5, lane = tid & 31;
    const int g = lane >> 2, tg = lane & 3;
    const int wm = (wid >> 2) * 32, wn = (wid & 3) * 32;   // 4m x 4n warps
    const int mrow0 = blockIdx.y * 128;
    const int ncol0 = blockIdx.x * 128;

    const int NI0 = K0 / 32;
    const int NI = NI0 + K1 / 32;

    float acc[2][4][4];
#pragma unroll
    for (int i = 0; i < 2; i++)
#pragma unroll
        for (int j = 0; j < 4; j++)
#pragma unroll
            for (int q = 0; q < 4; q++) acc[i][j][q] = 0.f;

    // A-fill: 512 threads, 128 rows x 32 floats -> 8 floats (2 float4) each
    const int ar = tid >> 2, ah = (tid & 3) * 8;
    // B-fill: hl = tid>>8, row = (tid&255)>>1, seg = tid&1 (2 x 16B each)
    const int bhl = tid >> 8, br = (tid & 255) >> 1, bseg = (tid & 1) * 16;

#define A_SRC(A, K, koff) ((const float4*)((A) + (size_t)(mrow0 + ar) * (K) + (koff) + ah))
#define STS_A(buf, st)                                                                 \
    {                                                                                  \
        __nv_bfloat16* dh = sm + SM_A + ((buf) * 2 + 0) * TILE_HL + ar * PITCH + ah;   \
        __nv_bfloat16* dl = sm + SM_A + ((buf) * 2 + 1) * TILE_HL + ar * PITCH + ah;   \
        float f[8] = {st[0].x, st[0].y, st[0].z, st[0].w,                              \
                      st[1].x, st[1].y, st[1].z, st[1].w};                             \
        uint32_t hi2[4], lo2[4];                                                       \
        _Pragma("unroll")                                                              \
        for (int j = 0; j < 4; j++) {                                                  \
            __nv_bfloat16 h0 = __float2bfloat16(f[2 * j]);                             \
            __nv_bfloat16 h1 = __float2bfloat16(f[2 * j + 1]);                         \
            __nv_bfloat16 l0 = __float2bfloat16(f[2 * j] - __bfloat162float(h0));      \
            __nv_bfloat16 l1 = __float2bfloat16(f[2 * j + 1] - __bfloat162float(h1));  \
            hi2[j] = (uint32_t)__bfloat16_as_ushort(h0) |                              \
                     ((uint32_t)__bfloat16_as_ushort(h1) << 16);                       \
            lo2[j] = (uint32_t)__bfloat16_as_ushort(l0) |                              \
                     ((uint32_t)__bfloat16_as_ushort(l1) << 16);                       \
        }                                                                              \
        *(uint4*)dh = make_uint4(hi2[0], hi2[1], hi2[2], hi2[3]);                      \
        *(uint4*)dl = make_uint4(lo2[0], lo2[1], lo2[2], lo2[3]);                      \
    }
#define LOAD_B(buf, Bhi, Blo, K, koff)                                                 \
    {                                                                                  \
        const __nv_bfloat16* src = ((bhl) ? (Blo) : (Bhi)) +                           \
                                   (size_t)(ncol0 + br) * (K) + (koff) + bseg;         \
        __nv_bfloat16* dst = sm + SM_B + ((buf) * 2 + bhl) * TILE_HL + br * PITCH +    \
                             bseg;                                                     \
        cp_async16(dst, src);                                                          \
        cp_async16(dst + 8, src + 8);                                                  \
    }

    {
        float4 st[2];
        const float4* s4 = A_SRC(A0, K0, 0);
        st[0] = s4[0]; st[1] = s4[1];
        STS_A(0, st);
        LOAD_B(0, B0hi, B0lo, K0, 0);
        cp_commit();
    }

    for (int i = 0; i < NI; i++) {
        cp_wait<0>();
        __syncthreads();

        const int buf = i & 1;
        float4 st[2];
        bool have_next = (i + 1 < NI);
        if (have_next) {
            int ni = i + 1;
            if (ni < NI0) {
                const float4* s4 = A_SRC(A0, K0, ni * 32);
                st[0] = s4[0]; st[1] = s4[1];
                LOAD_B(buf ^ 1, B0hi, B0lo, K0, ni * 32);
            } else {
                int koff = (ni - NI0) * 32;
                const float4* s4 = A_SRC(A1, K1, koff);
                st[0] = s4[0]; st[1] = s4[1];
                LOAD_B(buf ^ 1, B1hi, B1lo, K1, koff);
            }
            cp_commit();
        }

        const __nv_bfloat16* sAh = sm + SM_A + (buf * 2 + 0) * TILE_HL;
        const __nv_bfloat16* sAl = sm + SM_A + (buf * 2 + 1) * TILE_HL;
        const __nv_bfloat16* sBh = sm + SM_B + (buf * 2 + 0) * TILE_HL;
        const __nv_bfloat16* sBl = sm + SM_B + (buf * 2 + 1) * TILE_HL;
#pragma unroll
        for (int kk = 0; kk < 32; kk += 16) {
            uint32_t bh[4][2], bl[4][2];
#pragma unroll
            for (int nt = 0; nt < 4; nt++) {
                int n = wn + nt * 8 + g;
                bh[nt][0] = *(const uint32_t*)(sBh + n * PITCH + kk + tg * 2);
                bh[nt][1] = *(const uint32_t*)(sBh + n * PITCH + kk + tg * 2 + 8);
                bl[nt][0] = *(const uint32_t*)(sBl + n * PITCH + kk + tg * 2);
                bl[nt][1] = *(const uint32_t*)(sBl + n * PITCH + kk + tg * 2 + 8);
            }
#pragma unroll
            for (int mt = 0; mt < 2; mt++) {
                int r = wm + mt * 16 + g;
                uint32_t a_hi[4], a_lo[4];
                a_hi[0] = *(const uint32_t*)(sAh + r * PITCH + kk + tg * 2);
                a_hi[1] = *(const uint32_t*)(sAh + (r + 8) * PITCH + kk + tg * 2);
                a_hi[2] = *(const uint32_t*)(sAh + r * PITCH + kk + tg * 2 + 8);
                a_hi[3] = *(const uint32_t*)(sAh + (r + 8) * PITCH + kk + tg * 2 + 8);
                a_lo[0] = *(const uint32_t*)(sAl + r * PITCH + kk + tg * 2);
                a_lo[1] = *(const uint32_t*)(sAl + (r + 8) * PITCH + kk + tg * 2);
                a_lo[2] = *(const uint32_t*)(sAl + r * PITCH + kk + tg * 2 + 8);
                a_lo[3] = *(const uint32_t*)(sAl + (r + 8) * PITCH + kk + tg * 2 + 8);
#pragma unroll
                for (int nt = 0; nt < 4; nt++) {
                    mma_bf16(acc[mt][nt], a_hi, bh[nt]);
                    mma_bf16(acc[mt][nt], a_lo, bh[nt]);
                    mma_bf16(acc[mt][nt], a_hi, bl[nt]);
                }
            }
        }

        if (have_next) STS_A(buf ^ 1, st);
    }

#pragma unroll
    for (int mt = 0; mt < 2; mt++) {
#pragma unroll
        for (int nt = 0; nt < 4; nt++) {
            int r0 = mrow0 + wm + mt * 16 + g;
            int c0 = ncol0 + wn + nt * 8 + tg * 2;
            *(float2*)(C + (size_t)r0 * 1024 + c0) =
                make_float2(acc[mt][nt][0], acc[mt][nt][1]);
            *(float2*)(C + (size_t)(r0 + 8) * 1024 + c0) =
                make_float2(acc[mt][nt][2], acc[mt][nt][3]);
        }
    }
#undef A_SRC
#undef STS_A
#undef LOAD_B
}

// ---------------- HMMA persistent recurrence v3 (R8, proven 5.5us/step) -----
#define R3_WP 1032
#define R3_SW (32 * R3_WP)
#define R3_HP 264
#define R3_HB (32 * R3_HP)
#define R3_HOFF (2 * R3_SW)
#define R3_RED_BYTE (R3_HOFF * 2)
#define R3_RPITCH 34
#define R3_RW (32 * R3_RPITCH)
#define R3_PRE_BYTE ((R3_HOFF + 4 * R3_HB) * 2)
#define R3_BYTES (R3_PRE_BYTE + 4096)

__global__ __launch_bounds__(256, 1) void recur3(
    const float* __restrict__ pre, float* __restrict__ out,
    const float* __restrict__ Wh,
    __nv_bfloat16* __restrict__ hhi, __nv_bfloat16* __restrict__ hlo,
    int steps)
{
    extern __shared__ __align__(16) __nv_bfloat16 sm2[];
    float* red  = (float*)((char*)sm2 + R3_RED_BYTE);
    float* preS = (float*)((char*)sm2 + R3_PRE_BYTE);
    const int tid = threadIdx.x, wid = tid >> 5, lane = tid & 31;
    const int g = lane >> 2, tg = lane & 3;
    const int rg = blockIdx.x >> 5;
    const int r0 = rg * 32;
    const int c0 = (blockIdx.x & 31) * 32;

    for (int k = wid; k < H_DIM; k += 8) {
        float w = Wh[(size_t)k * H_DIM + c0 + lane];
        __nv_bfloat16 h = __float2bfloat16(w);
        sm2[lane * R3_WP + k] = h;
        sm2[R3_SW + lane * R3_WP + k] = __float2bfloat16(w - __bfloat162float(h));
    }
    __syncthreads();

    unsigned target = 0;
    volatile unsigned* vb = &g_bar4[rg * 64];

#define ISSUE_H(c, buf, hp)                                                              \
    {                                                                                    \
        _Pragma("unroll")                                                                \
        for (int i = 0; i < 8; i++) {                                                    \
            int f = i * 256 + tid;                                                       \
            int hl = f >> 10, rem = f & 1023;                                            \
            int row = rem >> 5, seg = rem & 31;                                          \
            const __nv_bfloat16* src = (hl ? hlo : hhi) + (size_t)(hp)*BH +              \
                                       (size_t)(r0 + row) * H_DIM + (c)*256 + seg * 8;   \
            cp_async16(sm2 + R3_HOFF + ((buf)*2 + hl) * R3_HB + row * R3_HP + seg * 8,   \
                       src);                                                             \
        }                                                                                \
        cp_commit();                                                                     \
    }
#define ISSUE_PRE(tt)                                                                    \
    {                                                                                    \
        int row = tid >> 3, seg = tid & 7;                                               \
        cp_async16(preS + row * 32 + seg * 4,                                            \
                   pre + (size_t)(tt)*BH + (size_t)(r0 + row) * H_DIM + c0 + seg * 4);   \
        cp_commit();                                                                     \
    }

    for (int t = 0; t < steps; t++) {
        float acc[2][4][4];
#pragma unroll
        for (int mt = 0; mt < 2; mt++)
#pragma unroll
            for (int nt = 0; nt < 4; nt++)
#pragma unroll
                for (int q = 0; q < 4; q++) acc[mt][nt][q] = 0.f;

        if (t > 0) {
            const int hp = (t - 1) & 1;
            ISSUE_H(0, 0, hp);
            ISSUE_H(1, 1, hp);
            ISSUE_PRE(t);
#pragma unroll 1
            for (int c = 0; c < 4; c++) {
                if (c <= 1) cp_wait<2>();
                else if (c == 2) cp_wait<1>();
                else cp_wait<0>();
                __syncthreads();
                const int buf = c & 1;
                const __nv_bfloat16* sAh = sm2 + R3_HOFF + buf * 2 * R3_HB;
                const __nv_bfloat16* sAl = sAh + R3_HB;
                const int kl = wid * 32;
#pragma unroll
                for (int kt = 0; kt < 2; kt++) {
                    const int kk = kl + kt * 16;
                    const int kgl = c * 256 + kk;
                    uint32_t ah[2][4], al[2][4];
#pragma unroll
                    for (int mt = 0; mt < 2; mt++) {
                        const int ra = (mt * 16 + g) * R3_HP + kk + tg * 2;
                        const int rb = (mt * 16 + g + 8) * R3_HP + kk + tg * 2;
                        ah[mt][0] = *(const uint32_t*)(sAh + ra);
                        ah[mt][1] = *(const uint32_t*)(sAh + rb);
                        ah[mt][2] = *(const uint32_t*)(sAh + ra + 8);
                        ah[mt][3] = *(const uint32_t*)(sAh + rb + 8);
                        al[mt][0] = *(const uint32_t*)(sAl + ra);
                        al[mt][1] = *(const uint32_t*)(sAl + rb);
                        al[mt][2] = *(const uint32_t*)(sAl + ra + 8);
                        al[mt][3] = *(const uint32_t*)(sAl + rb + 8);
                    }
#pragma unroll
                    for (int nt = 0; nt < 4; nt++) {
                        const int nb = (nt * 8 + g) * R3_WP + kgl + tg * 2;
                        uint32_t bh[2], bl[2];
                        bh[0] = *(const uint32_t*)(sm2 + nb);
                        bh[1] = *(const uint32_t*)(sm2 + nb + 8);
                        bl[0] = *(const uint32_t*)(sm2 + R3_SW + nb);
                        bl[1] = *(const uint32_t*)(sm2 + R3_SW + nb + 8);
#pragma unroll
                        for (int mt = 0; mt < 2; mt++) {
                            mma_bf16(acc[mt][nt], ah[mt], bh);
                            mma_bf16(acc[mt][nt], al[mt], bh);
                            mma_bf16(acc[mt][nt], ah[mt], bl);
                        }
                    }
                }
                __syncthreads();
                if (c < 2) ISSUE_H(c + 2, c & 1, hp);
            }
            float* rw = red + wid * R3_RW;
#pragma unroll
            for (int mt = 0; mt < 2; mt++)
#pragma unroll
                for (int nt = 0; nt < 4; nt++) {
                    int row = mt * 16 + g, col = nt * 8 + tg * 2;
                    *(float2*)(rw + row * R3_RPITCH + col) =
                        make_float2(acc[mt][nt][0], acc[mt][nt][1]);
                    *(float2*)(rw + (row + 8) * R3_RPITCH + col) =
                        make_float2(acc[mt][nt][2], acc[mt][nt][3]);
                }
            __syncthreads();
        } else {
            ISSUE_PRE(0);
            cp_wait<0>();
            __syncthreads();
        }

        {
            const int row = tid >> 3, cseg = (tid & 7) * 4;
            float4 s = make_float4(0.f, 0.f, 0.f, 0.f);
            if (t > 0) {
#pragma unroll
                for (int w = 0; w < 8; w++) {
                    const float* rp = red + w * R3_RW + row * R3_RPITCH + cseg;
                    s.x += rp[0]; s.y += rp[1]; s.z += rp[2]; s.w += rp[3];
                }
            }
            const float4 p = *(const float4*)(preS + row * 32 + cseg);
            float v0 = tanhf(p.x + s.x), v1 = tanhf(p.y + s.y);
            float v2 = tanhf(p.z + s.z), v3 = tanhf(p.w + s.w);
            const size_t gidx = (size_t)(r0 + row) * H_DIM + c0 + cseg;
            *(float4*)(out + (size_t)t * BH + gidx) = make_float4(v0, v1, v2, v3);

            __nv_bfloat16 h0 = __float2bfloat16(v0), h1 = __float2bfloat16(v1);
            __nv_bfloat16 h2 = __float2bfloat16(v2), h3 = __float2bfloat16(v3);
            __nv_bfloat16 l0 = __float2bfloat16(v0 - __bfloat162float(h0));
            __nv_bfloat16 l1 = __float2bfloat16(v1 - __bfloat162float(h1));
            __nv_bfloat16 l2 = __float2bfloat16(v2 - __bfloat162float(h2));
            __nv_bfloat16 l3 = __float2bfloat16(v3 - __bfloat162float(h3));
            const size_t hidx = (size_t)(t & 1) * BH + gidx;
            *(uint2*)(hhi + hidx) = make_uint2(
                (uint32_t)__bfloat16_as_ushort(h0) | ((uint32_t)__bfloat16_as_ushort(h1) << 16),
                (uint32_t)__bfloat16_as_ushort(h2) | ((uint32_t)__bfloat16_as_ushort(h3) << 16));
            *(uint2*)(hlo + hidx) = make_uint2(
                (uint32_t)__bfloat16_as_ushort(l0) | ((uint32_t)__bfloat16_as_ushort(l1) << 16),
                (uint32_t)__bfloat16_as_ushort(l2) | ((uint32_t)__bfloat16_as_ushort(l3) << 16));
        }

        if (t + 1 < steps) {
            __threadfence();
            __syncthreads();
            target += 32;
            if (tid == 0) {
                atomicAdd((unsigned*)vb, 1u);
                while (*vb < target) __nanosleep(32);
            }
            __syncthreads();
        }
    }
#undef ISSUE_H
#undef ISSUE_PRE
}

// ---------------- launch ----------------------------------------------------
extern "C" void kernel_launch(void* const* d_in, const int* in_sizes, int n_in,
                              void* d_out, int out_size)
{
    (void)in_sizes; (void)n_in; (void)out_size;
    const float* x   = (const float*)d_in[0];
    const float* Wi0 = (const float*)d_in[1];
    const float* Wh0 = (const float*)d_in[2];
    const float* Ws0 = (const float*)d_in[3];
    const float* Wi1 = (const float*)d_in[4];
    const float* Wh1 = (const float*)d_in[5];
    const float* Ws1 = (const float*)d_in[6];
    float* out = (float*)d_out;

    void* p;
    cudaGetSymbolAddress(&p, g_pre);     float* pre = (float*)p;
    cudaGetSymbolAddress(&p, g_sx1);     float* sx1 = (float*)p;
    cudaGetSymbolAddress(&p, g_hhi);     __nv_bfloat16* hhi = (__nv_bfloat16*)p;
    cudaGetSymbolAddress(&p, g_hlo);     __nv_bfloat16* hlo = (__nv_bfloat16*)p;
    cudaGetSymbolAddress(&p, g_w0t_hi);  __nv_bfloat16* w0hi = (__nv_bfloat16*)p;
    cudaGetSymbolAddress(&p, g_w0t_lo);  __nv_bfloat16* w0lo = (__nv_bfloat16*)p;
    cudaGetSymbolAddress(&p, g_wi1t_hi); __nv_bfloat16* wi1hi = (__nv_bfloat16*)p;
    cudaGetSymbolAddress(&p, g_wi1t_lo); __nv_bfloat16* wi1lo = (__nv_bfloat16*)p;
    cudaGetSymbolAddress(&p, g_ws1t_hi); __nv_bfloat16* ws1hi = (__nv_bfloat16*)p;
    cudaGetSymbolAddress(&p, g_ws1t_lo); __nv_bfloat16* ws1lo = (__nv_bfloat16*)p;

    cudaFuncSetAttribute(recur3,
                         cudaFuncAttributeMaxDynamicSharedMemorySize, R3_BYTES);
    cudaFuncSetAttribute(tc_gemm,
                         cudaFuncAttributeMaxDynamicSharedMemorySize,
                         SM_TOTAL_BF16 * 2);

    // weight prep: transpose + bf16 hi/lo split
    dim3 tb(32, 8);
    k_tsplit<<<dim3(I_DIM / 32, H_DIM / 32), tb>>>(Wi0, Ws0, w0hi, w0lo, I_DIM, H_DIM);
    k_tsplit<<<dim3(H_DIM / 32, H_DIM / 32), tb>>>(Wi1, nullptr, wi1hi, wi1lo, H_DIM, H_DIM);
    k_tsplit<<<dim3(I_DIM / 32, H_DIM / 32), tb>>>(Ws1, nullptr, ws1hi, ws1lo, I_DIM, H_DIM);

    // layer 0: pre0 = x @ (Wi0+Ws0)
    tc_gemm<<<dim3(H_DIM / 128, (T_DIM * B_DIM) / 128), 512, SM_TOTAL_BF16 * 2>>>(
        pre, x, I_DIM, w0hi, w0lo, nullptr, 0, nullptr, nullptr);

    k_reset_bar<<<1, 256>>>();
    recur3<<<128, 256, R3_BYTES>>>(pre, out, Wh0, hhi, hlo, T_DIM);

    // layer 1: pre1 = out0[1:] @ Wi1 + sx1 @ Ws1  (fused)
    int nsx = (T_DIM - 1) * B_DIM * I_DIM;
    k_sx1<<<(nsx + 255) / 256, 256>>>(x, sx1, nsx, B_DIM * I_DIM);
    tc_gemm<<<dim3(H_DIM / 128, ((T_DIM - 1) * B_DIM) / 128), 512, SM_TOTAL_BF16 * 2>>>(
        pre, out + BH, H_DIM, wi1hi, wi1lo, sx1, I_DIM, ws1hi, ws1lo);

    k_reset_bar<<<1, 256>>>();
    recur3<<<128, 256, R3_BYTES>>>(pre, out + (size_t)T_DIM * BH, Wh1, hhi, hlo, T_DIM - 1);
}